// round 7
// baseline (speedup 1.0000x reference)
#include <cuda_runtime.h>

typedef unsigned long long ULL;

// gx scratch: [B=256][T=512][G=512] fp32 = 256 MiB (module BSS; no runtime alloc)
__device__ __align__(16) float g_gx[256u * 512u * 512u];

__device__ __forceinline__ void ffma2(ULL& d, ULL a, ULL b) {
    asm("fma.rn.f32x2 %0, %1, %2, %0;" : "+l"(d) : "l"(a), "l"(b));
}
__device__ __forceinline__ ULL dup2(float x) {
    ULL r; asm("mov.b64 %0, {%1, %1};" : "=l"(r) : "f"(x)); return r;
}
__device__ __forceinline__ float2 unpack2(ULL v) {
    float2 f; asm("mov.b64 {%0, %1}, %2;" : "=f"(f.x), "=f"(f.y) : "l"(v)); return f;
}

__device__ __forceinline__ float sigmoidf_(float x) {
    return 1.0f / (1.0f + __expf(-x));
}
__device__ __forceinline__ float tanhf_(float x) {
    float ax = fabsf(x);
    float e = __expf(-2.0f * ax);          // in (0,1], no overflow
    float t = (1.0f - e) / (1.0f + e);
    return copysignf(t, x);
}

// ---------------------------------------------------------------------------
// Kernel 1: gx[m][n] = sum_k X[m][k] * W_ih[n][k] + (b_ih[n] + b_hh[n])
// M = 131072 (m = b*512 + t), N = 512, K = 300.
// Tiles: BM=128, BN=128, BK=8; 256 threads; 8x8 micro-tile per thread,
// accumulators packed as f32x2 along n. Double-buffered smem, one sync/iter.
// Blocks whose whole t-range is masked (t0 >= length[b]) are skipped.
// ---------------------------------------------------------------------------
__device__ __forceinline__ void gemm_compute_tile(
    const float* __restrict__ ab, const float* __restrict__ bb,
    int m0, int n0, ULL (&acc)[8][4])
{
#pragma unroll
    for (int kk = 0; kk < 8; ++kk) {
        float4 a0 = *(const float4*)(ab + kk * 132 + m0);
        float4 a1 = *(const float4*)(ab + kk * 132 + m0 + 4);
        ulonglong2 bb0 = *(const ulonglong2*)(bb + kk * 132 + n0);
        ulonglong2 bb1 = *(const ulonglong2*)(bb + kk * 132 + n0 + 4);
        float av[8] = {a0.x, a0.y, a0.z, a0.w, a1.x, a1.y, a1.z, a1.w};
#pragma unroll
        for (int i = 0; i < 8; ++i) {
            ULL ad = dup2(av[i]);
            ffma2(acc[i][0], ad, bb0.x);
            ffma2(acc[i][1], ad, bb0.y);
            ffma2(acc[i][2], ad, bb1.x);
            ffma2(acc[i][3], ad, bb1.y);
        }
    }
}

__global__ __launch_bounds__(256, 2)
void k_gemm_gx(const float* __restrict__ X, const float* __restrict__ W,
               const float* __restrict__ b_ih, const float* __restrict__ b_hh,
               const int* __restrict__ lengths)
{
    const int bm = blockIdx.x;            // 0..1023  (m block)
    const int bn = blockIdx.y;            // 0..3     (n block)
    const int bseq = bm >> 2;             // batch index (512 t / 128 = 4 blocks/b)
    const int tblk = bm & 3;
    if (tblk * 128 >= lengths[bseq]) return;   // whole block masked out

    __shared__ __align__(16) float As[2 * 8 * 132];
    __shared__ __align__(16) float Bs[2 * 8 * 132];

    const int tid = threadIdx.x;
    const int ty = tid >> 4, tx = tid & 15;
    const int m0 = ty * 8, n0 = tx * 8;
    const int lrow = tid >> 1;            // 0..127
    const int kb = (tid & 1) * 4;         // 0 or 4
    const int bm0 = bm * 128;
    const int bn0 = bn * 128;

    const float* Arow = X + (size_t)(bm0 + lrow) * 300 + kb;
    const float* Brow = W + (size_t)(bn0 + lrow) * 300 + kb;

    ULL acc[8][4];
#pragma unroll
    for (int i = 0; i < 8; ++i)
#pragma unroll
        for (int j = 0; j < 4; ++j) acc[i][j] = 0ull;

    // prologue: stage k0 = 0 into buffer 0 (kb in {0,4}, k<300 always here)
    {
        float4 fa = *(const float4*)(Arow);
        float4 fb = *(const float4*)(Brow);
        float* a = As; float* b = Bs;
        a[(kb + 0) * 132 + lrow] = fa.x; a[(kb + 1) * 132 + lrow] = fa.y;
        a[(kb + 2) * 132 + lrow] = fa.z; a[(kb + 3) * 132 + lrow] = fa.w;
        b[(kb + 0) * 132 + lrow] = fb.x; b[(kb + 1) * 132 + lrow] = fb.y;
        b[(kb + 2) * 132 + lrow] = fb.z; b[(kb + 3) * 132 + lrow] = fb.w;
    }
    __syncthreads();

#pragma unroll 1
    for (int it = 1; it < 38; ++it) {      // 38 k-tiles cover K=300 (zero-padded)
        int k = it * 8 + kb;
        float4 na, nb;
        if (k < 300) {                      // k <= 296 -> full float4 in-bounds
            na = *(const float4*)(Arow + it * 8);
            nb = *(const float4*)(Brow + it * 8);
        } else {
            na = make_float4(0.f, 0.f, 0.f, 0.f);
            nb = na;
        }
        gemm_compute_tile(As + ((it - 1) & 1) * 1056,
                          Bs + ((it - 1) & 1) * 1056, m0, n0, acc);
        {
            float* a = As + (it & 1) * 1056;
            float* b = Bs + (it & 1) * 1056;
            a[(kb + 0) * 132 + lrow] = na.x; a[(kb + 1) * 132 + lrow] = na.y;
            a[(kb + 2) * 132 + lrow] = na.z; a[(kb + 3) * 132 + lrow] = na.w;
            b[(kb + 0) * 132 + lrow] = nb.x; b[(kb + 1) * 132 + lrow] = nb.y;
            b[(kb + 2) * 132 + lrow] = nb.z; b[(kb + 3) * 132 + lrow] = nb.w;
        }
        __syncthreads();
    }
    gemm_compute_tile(As + 1056, Bs + 1056, m0, n0, acc);  // buffer 37&1 = 1

    // epilogue: add bias, store
    float bias[8];
#pragma unroll
    for (int j = 0; j < 8; ++j)
        bias[j] = b_ih[bn0 + n0 + j] + b_hh[bn0 + n0 + j];

#pragma unroll
    for (int i = 0; i < 8; ++i) {
        float2 v0 = unpack2(acc[i][0]);
        float2 v1 = unpack2(acc[i][1]);
        float2 v2 = unpack2(acc[i][2]);
        float2 v3 = unpack2(acc[i][3]);
        float4 o0 = make_float4(v0.x + bias[0], v0.y + bias[1],
                                v1.x + bias[2], v1.y + bias[3]);
        float4 o1 = make_float4(v2.x + bias[4], v2.y + bias[5],
                                v3.x + bias[6], v3.y + bias[7]);
        size_t row = (size_t)(bm0 + m0 + i) * 512 + bn0 + n0;
        *(float4*)&g_gx[row]     = o0;
        *(float4*)&g_gx[row + 4] = o1;
    }
}

// ---------------------------------------------------------------------------
// Kernel 2: LSTM recurrence + final FC.
// 128 CTAs x 256 threads. CTA owns batch rows b0, b0+1. Thread tid owns gate
// rows r0=tid, r1=tid+256 of W_hh (128 floats each): first half of each row in
// registers (64 regs/row -> 128 weight regs/thread), second half in smem
// (128 KB/CTA). Dot products use packed f32x2 FMA along k. Gates exchanged via
// smem; h,c update masked by t < length[b]; loop runs to max(len0,len1).
// ---------------------------------------------------------------------------
#define K2_SMEM_BYTES (32 * 256 * 16 + 2 * 128 * 4 + 2 * 512 * 4)

__global__ __launch_bounds__(256, 1)
void k_lstm(const float* __restrict__ Whh, const float* __restrict__ fcw,
            const float* __restrict__ fcb, const int* __restrict__ lengths,
            float* __restrict__ out)
{
    extern __shared__ __align__(16) float sm[];
    ulonglong2* sw = (ulonglong2*)sm;           // [32][256] float4-as-ull2 = 128 KB
    float* hbuf = sm + 32768;                   // [2][128]
    float* gsm  = hbuf + 256;                   // [2][512]

    const int tid = threadIdx.x;
    const int b0 = blockIdx.x * 2;
    const int r0 = tid, r1 = tid + 256;

    // load weights: per row 32 float4 (=ull2); j 0..15 -> regs, 16..31 -> smem
    ulonglong2 wr0[16], wr1[16];
    {
        const ulonglong2* w0 = (const ulonglong2*)(Whh + (size_t)r0 * 128);
        const ulonglong2* w1 = (const ulonglong2*)(Whh + (size_t)r1 * 128);
#pragma unroll
        for (int j = 0; j < 16; ++j) { wr0[j] = w0[j]; wr1[j] = w1[j]; }
#pragma unroll
        for (int j = 0; j < 16; ++j) {
            sw[j * 256 + tid]        = w0[16 + j];
            sw[(16 + j) * 256 + tid] = w1[16 + j];
        }
    }
    if (tid < 128) { hbuf[tid] = 0.0f; hbuf[128 + tid] = 0.0f; }

    const int ub = tid >> 7;          // which batch row this thread updates
    const int uj = tid & 127;         // which h element
    const int len0 = lengths[b0];
    const int len1 = lengths[b0 + 1];
    const int mylen = (ub == 0) ? len0 : len1;
    const int tmax = (len0 > len1) ? len0 : len1;
    float creg = 0.0f;

    const float* gxp0 = g_gx + (size_t)b0 * 512 * 512;
    const float* gxp1 = g_gx + (size_t)(b0 + 1) * 512 * 512;
    __syncthreads();

    for (int t = 0; t < tmax; ++t) {
        // prefetch gx early; consumed only after the dot phase
        const float gx00 = gxp0[(size_t)t * 512 + r0];   // (b0, r0)
        const float gx01 = gxp0[(size_t)t * 512 + r1];   // (b0, r1)
        const float gx10 = gxp1[(size_t)t * 512 + r0];   // (b1, r0)
        const float gx11 = gxp1[(size_t)t * 512 + r1];   // (b1, r1)

        ULL a00 = 0ull, a01 = 0ull, a10 = 0ull, a11 = 0ull;
        const ulonglong2* h0 = (const ulonglong2*)hbuf;
        const ulonglong2* h1 = (const ulonglong2*)(hbuf + 128);

#pragma unroll
        for (int j = 0; j < 16; ++j) {           // register-resident weight half
            ulonglong2 hv0 = h0[j], hv1 = h1[j];
            ulonglong2 w0 = wr0[j], w1 = wr1[j];
            ffma2(a00, w0.x, hv0.x); ffma2(a00, w0.y, hv0.y);
            ffma2(a01, w0.x, hv1.x); ffma2(a01, w0.y, hv1.y);
            ffma2(a10, w1.x, hv0.x); ffma2(a10, w1.y, hv0.y);
            ffma2(a11, w1.x, hv1.x); ffma2(a11, w1.y, hv1.y);
        }
#pragma unroll
        for (int j = 0; j < 16; ++j) {           // smem weight half
            ulonglong2 hv0 = h0[16 + j], hv1 = h1[16 + j];
            ulonglong2 w0 = sw[j * 256 + tid];
            ulonglong2 w1 = sw[(16 + j) * 256 + tid];
            ffma2(a00, w0.x, hv0.x); ffma2(a00, w0.y, hv0.y);
            ffma2(a01, w0.x, hv1.x); ffma2(a01, w0.y, hv1.y);
            ffma2(a10, w1.x, hv0.x); ffma2(a10, w1.y, hv0.y);
            ffma2(a11, w1.x, hv1.x); ffma2(a11, w1.y, hv1.y);
        }

        float2 v;
        v = unpack2(a00); gsm[r0]       = v.x + v.y + gx00;
        v = unpack2(a10); gsm[r1]       = v.x + v.y + gx01;
        v = unpack2(a01); gsm[512 + r0] = v.x + v.y + gx10;
        v = unpack2(a11); gsm[512 + r1] = v.x + v.y + gx11;
        __syncthreads();

        // update phase: 256 threads cover 2 rows x 128 h-elements
        {
            const float gi = gsm[ub * 512 + uj];
            const float gf = gsm[ub * 512 + 128 + uj];
            const float gg = gsm[ub * 512 + 256 + uj];
            const float go = gsm[ub * 512 + 384 + uj];
            const float i_ = sigmoidf_(gi);
            const float f_ = sigmoidf_(gf);
            const float g_ = tanhf_(gg);
            const float o_ = sigmoidf_(go);
            const float cn = f_ * creg + i_ * g_;
            const float hn = o_ * tanhf_(cn);
            const bool valid = (t < mylen);
            const float hold = hbuf[ub * 128 + uj];
            creg = valid ? cn : creg;
            hbuf[ub * 128 + uj] = valid ? hn : hold;
        }
        __syncthreads();
    }

    // final FC: out[b][c] = h[b] . fc_w[c] + fc_b[c]   (12 tiny dots)
    if (tid < 12) {
        const int bb = tid / 6, c = tid % 6;
        const float* h = hbuf + bb * 128;
        const float* w = fcw + c * 128;
        float s = fcb[c];
#pragma unroll 8
        for (int k = 0; k < 128; ++k) s += h[k] * w[k];
        out[(b0 + bb) * 6 + c] = s;
    }
}

// ---------------------------------------------------------------------------
extern "C" void kernel_launch(void* const* d_in, const int* in_sizes, int n_in,
                              void* d_out, int out_size)
{
    (void)in_sizes; (void)n_in; (void)out_size;
    const float* x       = (const float*)d_in[0];   // [256][512][300]
    const float* W_ih    = (const float*)d_in[1];   // [512][300]
    const float* W_hh    = (const float*)d_in[2];   // [512][128]
    const float* b_ih    = (const float*)d_in[3];   // [512]
    const float* b_hh    = (const float*)d_in[4];   // [512]
    const float* fc_w    = (const float*)d_in[5];   // [6][128]
    const float* fc_b    = (const float*)d_in[6];   // [6]
    const int*   lengths = (const int*)d_in[7];     // [256]
    float* out = (float*)d_out;                     // [256][6]

    dim3 g1(1024, 4);
    k_gemm_gx<<<g1, 256>>>(x, W_ih, b_ih, b_hh, lengths);

    (void)cudaFuncSetAttribute(k_lstm,
                               cudaFuncAttributeMaxDynamicSharedMemorySize,
                               K2_SMEM_BYTES);
    k_lstm<<<128, 256, K2_SMEM_BYTES>>>(W_hh, fc_w, fc_b, lengths, out);
}